// round 1
// baseline (speedup 1.0000x reference)
#include <cuda_runtime.h>
#include <cuda_bf16.h>
#include <math.h>

#define N_NODES 50000
#define N_EDGES 800000
#define C 128
#define TE 128          // edges per tile
#define HS_STRIDE 132   // padded stride for transposed h tile

// ---------------- scratch (static device globals; no allocations) -------------
__device__ float g_pq[(size_t)N_NODES * 256];   // [N][256]: p (cols 0..127, +b1), q (cols 128..255)
__device__ float g_agg[(size_t)N_NODES * C];    // max-aggregation buffer
__device__ float g_x[(size_t)N_NODES * C];      // inter-layer node features
__device__ float g_Wc[C * 256];                 // [k][0..127]=W1_top-W1_bot, [k][128..255]=W1_bot

// ---------------- float atomic max (signed-max / unsigned-min trick) ----------
__device__ __forceinline__ void atomicMaxF(float* a, float v) {
    if (v >= 0.0f) atomicMax((int*)a, __float_as_int(v));
    else           atomicMin((unsigned int*)a, __float_as_uint(v));
}

// ---------------- prep: Wc from W1 --------------------------------------------
__global__ void prep_kernel(const float* __restrict__ W1, float* __restrict__ Wc) {
    int k = blockIdx.x;        // 0..127
    int j = threadIdx.x;       // 0..255
    if (j < C) {
        Wc[k * 256 + j] = W1[k * C + j] - W1[(C + k) * C + j];
    } else {
        Wc[k * 256 + j] = W1[(C + k) * C + (j - C)];
    }
}

// ---------------- node GEMM: pq = x @ Wc (+ b1 on p half) ---------------------
__global__ void __launch_bounds__(256) node_gemm_kernel(
    const float* __restrict__ x, const float* __restrict__ Wc,
    const float* __restrict__ b1, float* __restrict__ pq, int N)
{
    __shared__ float xs[32 * C];
    int m0 = blockIdx.x * 32;
    int tid = threadIdx.x;

    // load 32 x 128 tile of x (float4), zero-pad tail
    for (int i = tid; i < 32 * C / 4; i += 256) {
        int r = i / (C / 4);
        int cc = i % (C / 4);
        float4 v = make_float4(0.f, 0.f, 0.f, 0.f);
        if (m0 + r < N) v = ((const float4*)(x + (size_t)(m0 + r) * C))[cc];
        ((float4*)xs)[i] = v;
    }
    __syncthreads();

    int col = tid;  // 0..255
    float acc[32];
#pragma unroll
    for (int r = 0; r < 32; r++) acc[r] = 0.f;

#pragma unroll 4
    for (int k = 0; k < C; k++) {
        float w = Wc[k * 256 + col];
#pragma unroll
        for (int r = 0; r < 32; r++) acc[r] = fmaf(xs[r * C + k], w, acc[r]);
    }

    float bias = (col < C) ? b1[col] : 0.f;
#pragma unroll
    for (int r = 0; r < 32; r++) {
        if (m0 + r < N) pq[(size_t)(m0 + r) * 256 + col] = acc[r] + bias;
    }
}

// ---------------- edge GEMM + max aggregation ---------------------------------
// h[e][k] = relu(p[dst[e]][k] + q[src[e]][k]); u = h @ W2; agg[dst] = max(agg, u)
__global__ void __launch_bounds__(256, 1) edge_kernel(
    const float* __restrict__ pq, const int* __restrict__ src,
    const int* __restrict__ dst, const float* __restrict__ W2,
    float* __restrict__ agg, int E)
{
    extern __shared__ float sm[];
    float* W2s = sm;                 // [128][128]
    float* hsT = sm + C * C;         // [128 ch][HS_STRIDE] transposed h tile
    __shared__ int sidx[2 * TE];     // [0..127]=dst, [128..255]=src

    int tid = threadIdx.x;

    // cache W2 (row-major [k][c]) in smem
    for (int i = tid * 4; i < C * C; i += 256 * 4)
        *(float4*)(W2s + i) = *(const float4*)(W2 + i);

    int cg = tid & 15;               // 16 col groups
    int rg = tid >> 4;               // 16 row groups
    int c0 = cg * 8, r0 = rg * 8;

    int ntiles = (E + TE - 1) / TE;
    for (int tile = blockIdx.x; tile < ntiles; tile += gridDim.x) {
        int e0 = tile * TE;
        __syncthreads();   // prev tile fully consumed before overwrite

        // load indices
        {
            int e = (tid < TE) ? tid : (tid - TE);
            int g = e0 + e;
            const int* arr = (tid < TE) ? dst : src;
            sidx[tid] = (g < E) ? arr[g] : 0;
        }
        __syncthreads();

        // gather: 2 threads per edge, 64 channels each; write transposed
        {
            int e = tid >> 1;
            int ch = (tid & 1) * 64;
            const float4* prow = (const float4*)(pq + (size_t)sidx[e] * 256) + (ch >> 2);
            const float4* qrow = (const float4*)(pq + (size_t)sidx[TE + e] * 256 + C) + (ch >> 2);
#pragma unroll
            for (int i = 0; i < 16; i++) {
                float4 a = prow[i];
                float4 b = qrow[i];
                int c = ch + i * 4;
                hsT[(c + 0) * HS_STRIDE + e] = fmaxf(a.x + b.x, 0.f);
                hsT[(c + 1) * HS_STRIDE + e] = fmaxf(a.y + b.y, 0.f);
                hsT[(c + 2) * HS_STRIDE + e] = fmaxf(a.z + b.z, 0.f);
                hsT[(c + 3) * HS_STRIDE + e] = fmaxf(a.w + b.w, 0.f);
            }
        }
        __syncthreads();

        // 128x128x128 GEMM, 8x8 micro-tile per thread
        float acc[8][8];
#pragma unroll
        for (int r = 0; r < 8; r++)
#pragma unroll
            for (int c = 0; c < 8; c++) acc[r][c] = 0.f;

#pragma unroll 4
        for (int k = 0; k < C; k++) {
            float4 w0 = *(const float4*)(W2s + k * C + c0);
            float4 w1 = *(const float4*)(W2s + k * C + c0 + 4);
            float4 h0 = *(const float4*)(hsT + k * HS_STRIDE + r0);
            float4 h1 = *(const float4*)(hsT + k * HS_STRIDE + r0 + 4);
            float hv[8] = {h0.x, h0.y, h0.z, h0.w, h1.x, h1.y, h1.z, h1.w};
            float wv[8] = {w0.x, w0.y, w0.z, w0.w, w1.x, w1.y, w1.z, w1.w};
#pragma unroll
            for (int r = 0; r < 8; r++)
#pragma unroll
                for (int c = 0; c < 8; c++)
                    acc[r][c] = fmaf(hv[r], wv[c], acc[r][c]);
        }

        // epilogue: read current max, skip losing atomics (race-safe: monotone)
#pragma unroll
        for (int r = 0; r < 8; r++) {
            int e = r0 + r;
            if (e0 + e < E) {
                int dn = sidx[e];
                float* arow = agg + (size_t)dn * C + c0;
                float4 cur0 = *(const float4*)arow;
                float4 cur1 = *(const float4*)(arow + 4);
                float cv[8] = {cur0.x, cur0.y, cur0.z, cur0.w,
                               cur1.x, cur1.y, cur1.z, cur1.w};
#pragma unroll
                for (int c = 0; c < 8; c++) {
                    float v = acc[r][c];
                    if (!(v <= cv[c])) atomicMaxF(arow + c, v);  // NaN-init -> always fires first
                }
            }
        }
    }
}

// ---------------- finalize: handle empty nodes, +b2, optional relu ------------
__global__ void finalize_kernel(const float* __restrict__ agg,
                                const float* __restrict__ b2,
                                float* __restrict__ out, int N, int do_relu)
{
    int idx = blockIdx.x * blockDim.x + threadIdx.x;
    if (idx >= N * C) return;
    int c = idx & (C - 1);
    float v = agg[idx];
    float o = isfinite(v) ? (v + b2[c]) : 0.f;
    if (do_relu) o = fmaxf(o, 0.f);
    out[idx] = o;
}

// ---------------- launch -------------------------------------------------------
extern "C" void kernel_launch(void* const* d_in, const int* in_sizes, int n_in,
                              void* d_out, int out_size)
{
    const float* x  = (const float*)d_in[0];
    const int*   ei = (const int*)d_in[1];
    int N = in_sizes[0] / C;
    int E = in_sizes[1] / 2;
    const int* srcp = ei;
    const int* dstp = ei + E;

    float *pq, *aggp, *xcur, *Wc;
    cudaGetSymbolAddress((void**)&pq,   g_pq);
    cudaGetSymbolAddress((void**)&aggp, g_agg);
    cudaGetSymbolAddress((void**)&xcur, g_x);
    cudaGetSymbolAddress((void**)&Wc,   g_Wc);

    const size_t SMEM = (size_t)(C * C + C * HS_STRIDE) * sizeof(float);
    cudaFuncSetAttribute(edge_kernel, cudaFuncAttributeMaxDynamicSharedMemorySize, (int)SMEM);

    const float* Ws[3][4] = {
        {(const float*)d_in[2],  (const float*)d_in[3],  (const float*)d_in[4],  (const float*)d_in[5]},
        {(const float*)d_in[6],  (const float*)d_in[7],  (const float*)d_in[8],  (const float*)d_in[9]},
        {(const float*)d_in[10], (const float*)d_in[11], (const float*)d_in[12], (const float*)d_in[13]},
    };

    const float* xin = x;
    for (int l = 0; l < 3; l++) {
        const float* W1 = Ws[l][0];
        const float* b1 = Ws[l][1];
        const float* W2 = Ws[l][2];
        const float* b2 = Ws[l][3];
        float* xout = (l == 2) ? (float*)d_out : xcur;

        prep_kernel<<<C, 256>>>(W1, Wc);
        node_gemm_kernel<<<(N + 31) / 32, 256>>>(xin, Wc, b1, pq, N);
        cudaMemsetAsync(aggp, 0xFF, (size_t)N * C * sizeof(float));
        edge_kernel<<<152, 256, SMEM>>>(pq, srcp, dstp, W2, aggp, E);
        finalize_kernel<<<(N * C + 255) / 256, 256>>>(aggp, b2, xout, N, (l < 2) ? 1 : 0);

        xin = xcur;
    }
}

// round 2
// speedup vs baseline: 1.0151x; 1.0151x over previous
#include <cuda_runtime.h>
#include <cuda_bf16.h>
#include <math.h>

#define N_NODES 50000
#define N_EDGES 800000
#define C 128
#define TE 128           // edges per tile
#define HST 136          // h tile stride (bf16 elems), conflict-free B-frag loads
#define DST 132          // D^T tile stride (floats)

// ---------------- scratch (static device globals; no allocations) -------------
__device__ float g_pq[(size_t)N_NODES * 256];      // [N][256]: p (+b1) | q
__device__ float g_agg[(size_t)N_NODES * C];       // max-aggregation buffer
__device__ float g_x[(size_t)N_NODES * C];         // inter-layer node features
__device__ float g_Wc[C * 256];                    // node-gemm combined W1
__device__ __nv_bfloat16 g_w2hi[C * C];            // W2^T hi plane [n][k]
__device__ __nv_bfloat16 g_w2lo[C * C];            // W2^T lo plane [n][k]

// ---------------- float atomic max (signed-max / unsigned-min trick) ----------
__device__ __forceinline__ void atomicMaxF(float* a, float v) {
    if (v >= 0.0f) atomicMax((int*)a, __float_as_int(v));
    else           atomicMin((unsigned int*)a, __float_as_uint(v));
}

// ---------------- HMMA m16n8k16 bf16 ------------------------------------------
__device__ __forceinline__ void mma16816(float& d0, float& d1, float& d2, float& d3,
                                         unsigned a0, unsigned a1, unsigned a2, unsigned a3,
                                         unsigned b0, unsigned b1)
{
    asm volatile(
        "mma.sync.aligned.m16n8k16.row.col.f32.bf16.bf16.f32 "
        "{%0,%1,%2,%3},{%4,%5,%6,%7},{%8,%9},{%0,%1,%2,%3};\n"
        : "+f"(d0), "+f"(d1), "+f"(d2), "+f"(d3)
        : "r"(a0), "r"(a1), "r"(a2), "r"(a3), "r"(b0), "r"(b1));
}

// ---------------- prep: Wc from W1 --------------------------------------------
__global__ void prep_kernel(const float* __restrict__ W1, float* __restrict__ Wc) {
    int k = blockIdx.x;
    int j = threadIdx.x;
    if (j < C) Wc[k * 256 + j] = W1[k * C + j] - W1[(C + k) * C + j];
    else       Wc[k * 256 + j] = W1[(C + k) * C + (j - C)];
}

// ---------------- prep: split W2^T into bf16 hi/lo planes ----------------------
__global__ void w2split_kernel(const float* __restrict__ W2,
                               __nv_bfloat16* __restrict__ hi,
                               __nv_bfloat16* __restrict__ lo) {
    int n = blockIdx.x;   // out channel
    int k = threadIdx.x;  // in channel
    float w = W2[k * C + n];
    __nv_bfloat16 h = __float2bfloat16(w);
    hi[n * C + k] = h;
    lo[n * C + k] = __float2bfloat16(w - __bfloat162float(h));
}

// ---------------- node GEMM: pq = x @ Wc (+ b1 on p half) ---------------------
__global__ void __launch_bounds__(256) node_gemm_kernel(
    const float* __restrict__ x, const float* __restrict__ Wc,
    const float* __restrict__ b1, float* __restrict__ pq, int N)
{
    __shared__ float xs[32 * C];
    int m0 = blockIdx.x * 32;
    int tid = threadIdx.x;

    for (int i = tid; i < 32 * C / 4; i += 256) {
        int r = i / (C / 4);
        int cc = i % (C / 4);
        float4 v = make_float4(0.f, 0.f, 0.f, 0.f);
        if (m0 + r < N) v = ((const float4*)(x + (size_t)(m0 + r) * C))[cc];
        ((float4*)xs)[i] = v;
    }
    __syncthreads();

    int col = tid;
    float acc[32];
#pragma unroll
    for (int r = 0; r < 32; r++) acc[r] = 0.f;

#pragma unroll 4
    for (int k = 0; k < C; k++) {
        float w = Wc[k * 256 + col];
#pragma unroll
        for (int r = 0; r < 32; r++) acc[r] = fmaf(xs[r * C + k], w, acc[r]);
    }

    float bias = (col < C) ? b1[col] : 0.f;
#pragma unroll
    for (int r = 0; r < 32; r++)
        if (m0 + r < N) pq[(size_t)(m0 + r) * 256 + col] = acc[r] + bias;
}

// ---------------- edge GEMM (tensor cores, split-bf16) + max aggregation ------
// h[e][k] = relu(p[dst[e]][k] + q[src[e]][k]); u = h @ W2; agg[dst] = max(agg, u)
// A = W2^T (M=out channels, held in regs), B = h^T (N=edges), K = hidden.
__global__ void __launch_bounds__(256, 1) edge_mma_kernel(
    const float* __restrict__ pq, const int* __restrict__ src,
    const int* __restrict__ dst,
    const __nv_bfloat16* __restrict__ W2hi, const __nv_bfloat16* __restrict__ W2lo,
    float* __restrict__ agg, int E)
{
    extern __shared__ char smraw[];
    __nv_bfloat16* h_hi = (__nv_bfloat16*)smraw;           // [128][HST]
    __nv_bfloat16* h_lo = h_hi + TE * HST;                 // [128][HST]
    float* DT = (float*)(h_lo + TE * HST);                 // [128][DST]  (u^T)
    __shared__ int sidx[2 * TE];

    int tid = threadIdx.x;
    int wid = tid >> 5, lane = tid & 31;
    int g = lane >> 2, tig = lane & 3;
    int m0 = wid * 16;   // this warp's 16 output channels

    // Preload A fragments (W2^T, both planes, all 8 k-steps) into registers.
    unsigned ah[8][4], al[8][4];
    {
        const unsigned* Hp = (const unsigned*)W2hi;
        const unsigned* Lp = (const unsigned*)W2lo;
#pragma unroll
        for (int ks = 0; ks < 8; ks++) {
            int k0 = ks * 16;
            int i00 = (m0 + g) * (C / 2) + (k0 + tig * 2) / 2;  // uint index
            ah[ks][0] = Hp[i00];
            ah[ks][1] = Hp[i00 + 8 * (C / 2)];
            ah[ks][2] = Hp[i00 + 4];
            ah[ks][3] = Hp[i00 + 8 * (C / 2) + 4];
            al[ks][0] = Lp[i00];
            al[ks][1] = Lp[i00 + 8 * (C / 2)];
            al[ks][2] = Lp[i00 + 4];
            al[ks][3] = Lp[i00 + 8 * (C / 2) + 4];
        }
    }

    int ntiles = (E + TE - 1) / TE;
    for (int tile = blockIdx.x; tile < ntiles; tile += gridDim.x) {
        int e0 = tile * TE;
        __syncthreads();  // prev tile fully consumed

        // load indices
        {
            int e = (tid < TE) ? tid : (tid - TE);
            int gidx = e0 + e;
            const int* arr = (tid < TE) ? dst : src;
            sidx[tid] = (gidx < E) ? arr[gidx] : 0;
        }
        __syncthreads();

        // gather + relu + bf16 split: 2 threads per edge, 64 channels each
        {
            int e = tid >> 1;
            int ch = (tid & 1) * 64;
            const float4* prow = (const float4*)(pq + (size_t)sidx[e] * 256) + (ch >> 2);
            const float4* qrow = (const float4*)(pq + (size_t)sidx[TE + e] * 256 + C) + (ch >> 2);
            unsigned* hhp = (unsigned*)(h_hi + e * HST + ch);
            unsigned* hlp = (unsigned*)(h_lo + e * HST + ch);
#pragma unroll
            for (int i = 0; i < 16; i++) {
                float4 a = prow[i];
                float4 b = qrow[i];
                float v0 = fmaxf(a.x + b.x, 0.f);
                float v1 = fmaxf(a.y + b.y, 0.f);
                float v2 = fmaxf(a.z + b.z, 0.f);
                float v3 = fmaxf(a.w + b.w, 0.f);
                __nv_bfloat162 hA = __floats2bfloat162_rn(v0, v1);
                __nv_bfloat162 hB = __floats2bfloat162_rn(v2, v3);
                __nv_bfloat162 lA = __floats2bfloat162_rn(v0 - __bfloat162float(hA.x),
                                                          v1 - __bfloat162float(hA.y));
                __nv_bfloat162 lB = __floats2bfloat162_rn(v2 - __bfloat162float(hB.x),
                                                          v3 - __bfloat162float(hB.y));
                hhp[i * 2 + 0] = *(unsigned*)&hA;
                hhp[i * 2 + 1] = *(unsigned*)&hB;
                hlp[i * 2 + 0] = *(unsigned*)&lA;
                hlp[i * 2 + 1] = *(unsigned*)&lB;
            }
        }
        __syncthreads();

        // MMA: 16 edge-tiles of 8, K=128 (8 k-steps), 3 split terms
#pragma unroll 1
        for (int et = 0; et < 16; et++) {
            int e0t = et * 8;
            float d0 = 0.f, d1 = 0.f, d2 = 0.f, d3 = 0.f;
#pragma unroll
            for (int ks = 0; ks < 8; ks++) {
                int k0 = ks * 16;
                const unsigned* bhp = (const unsigned*)(h_hi + (e0t + g) * HST + k0 + tig * 2);
                const unsigned* blp = (const unsigned*)(h_lo + (e0t + g) * HST + k0 + tig * 2);
                unsigned bh0 = bhp[0], bh1 = bhp[4];
                unsigned bl0 = blp[0], bl1 = blp[4];
                mma16816(d0, d1, d2, d3, ah[ks][0], ah[ks][1], ah[ks][2], ah[ks][3], bh0, bh1);
                mma16816(d0, d1, d2, d3, al[ks][0], al[ks][1], al[ks][2], al[ks][3], bh0, bh1);
                mma16816(d0, d1, d2, d3, ah[ks][0], ah[ks][1], ah[ks][2], ah[ks][3], bl0, bl1);
            }
            // D mapping: rows = channels (m0+g, m0+g+8), cols = edges (e0t+tig*2, +1)
            *(float2*)&DT[(m0 + g) * DST + e0t + tig * 2]     = make_float2(d0, d1);
            *(float2*)&DT[(m0 + g + 8) * DST + e0t + tig * 2] = make_float2(d2, d3);
        }
        __syncthreads();

        // epilogue: filtered atomic max, 2 threads per edge
        {
            int e = tid >> 1;
            if (e0 + e < E) {
                int dn = sidx[e];
                int ch = (tid & 1) * 64;
                float* arow = agg + (size_t)dn * C + ch;
#pragma unroll
                for (int i = 0; i < 16; i++) {
                    float4 cur = ((const float4*)arow)[i];
                    float v0 = DT[(ch + i * 4 + 0) * DST + e];
                    float v1 = DT[(ch + i * 4 + 1) * DST + e];
                    float v2 = DT[(ch + i * 4 + 2) * DST + e];
                    float v3 = DT[(ch + i * 4 + 3) * DST + e];
                    if (!(v0 <= cur.x)) atomicMaxF(arow + i * 4 + 0, v0);
                    if (!(v1 <= cur.y)) atomicMaxF(arow + i * 4 + 1, v1);
                    if (!(v2 <= cur.z)) atomicMaxF(arow + i * 4 + 2, v2);
                    if (!(v3 <= cur.w)) atomicMaxF(arow + i * 4 + 3, v3);
                }
            }
        }
    }
}

// ---------------- finalize: handle empty nodes, +b2, optional relu ------------
__global__ void finalize_kernel(const float* __restrict__ agg,
                                const float* __restrict__ b2,
                                float* __restrict__ out, int N, int do_relu)
{
    int idx = blockIdx.x * blockDim.x + threadIdx.x;
    if (idx >= N * C) return;
    int c = idx & (C - 1);
    float v = agg[idx];
    float o = isfinite(v) ? (v + b2[c]) : 0.f;
    if (do_relu) o = fmaxf(o, 0.f);
    out[idx] = o;
}

// ---------------- launch -------------------------------------------------------
extern "C" void kernel_launch(void* const* d_in, const int* in_sizes, int n_in,
                              void* d_out, int out_size)
{
    const float* x  = (const float*)d_in[0];
    const int*   ei = (const int*)d_in[1];
    int N = in_sizes[0] / C;
    int E = in_sizes[1] / 2;
    const int* srcp = ei;
    const int* dstp = ei + E;

    float *pq, *aggp, *xcur, *Wc;
    __nv_bfloat16 *w2hi, *w2lo;
    cudaGetSymbolAddress((void**)&pq,   g_pq);
    cudaGetSymbolAddress((void**)&aggp, g_agg);
    cudaGetSymbolAddress((void**)&xcur, g_x);
    cudaGetSymbolAddress((void**)&Wc,   g_Wc);
    cudaGetSymbolAddress((void**)&w2hi, g_w2hi);
    cudaGetSymbolAddress((void**)&w2lo, g_w2lo);

    const size_t SMEM = (size_t)(2 * TE * HST) * sizeof(__nv_bfloat16)
                      + (size_t)(C * DST) * sizeof(float);
    cudaFuncSetAttribute(edge_mma_kernel, cudaFuncAttributeMaxDynamicSharedMemorySize, (int)SMEM);

    const float* Ws[3][4] = {
        {(const float*)d_in[2],  (const float*)d_in[3],  (const float*)d_in[4],  (const float*)d_in[5]},
        {(const float*)d_in[6],  (const float*)d_in[7],  (const float*)d_in[8],  (const float*)d_in[9]},
        {(const float*)d_in[10], (const float*)d_in[11], (const float*)d_in[12], (const float*)d_in[13]},
    };

    const float* xin = x;
    for (int l = 0; l < 3; l++) {
        const float* W1 = Ws[l][0];
        const float* b1 = Ws[l][1];
        const float* W2 = Ws[l][2];
        const float* b2 = Ws[l][3];
        float* xout = (l == 2) ? (float*)d_out : xcur;

        prep_kernel<<<C, 256>>>(W1, Wc);
        w2split_kernel<<<C, C>>>(W2, w2hi, w2lo);
        node_gemm_kernel<<<(N + 31) / 32, 256>>>(xin, Wc, b1, pq, N);
        cudaMemsetAsync(aggp, 0xFF, (size_t)N * C * sizeof(float));
        edge_mma_kernel<<<148, 256, SMEM>>>(pq, srcp, dstp, w2hi, w2lo, aggp, E);
        finalize_kernel<<<(N * C + 255) / 256, 256>>>(aggp, b2, xout, N, (l < 2) ? 1 : 0);

        xin = xcur;
    }
}

// round 3
// speedup vs baseline: 1.2998x; 1.2805x over previous
#include <cuda_runtime.h>
#include <cuda_bf16.h>
#include <math.h>

#define N_NODES 50000
#define N_EDGES 800000
#define C 128
#define TE 128           // edges per tile
#define HST 136          // h tile stride (bf16), conflict-free B-frag loads (HST/2 mod 32 == 4)
#define DST 132          // D^T tile stride (floats)

// ---------------- scratch (static device globals; no allocations) -------------
__device__ float g_pq[(size_t)N_NODES * 256];      // [N][256]: p (+b1) | q
__device__ float g_agg[(size_t)N_NODES * C];       // max-aggregation buffer
__device__ float g_x[(size_t)N_NODES * C];         // inter-layer node features
__device__ float g_Wc[C * 256];                    // node-gemm combined W1
__device__ __nv_bfloat16 g_w2hi[C * C];            // W2^T hi plane [n][k]
__device__ __nv_bfloat16 g_w2lo[C * C];            // W2^T lo plane [n][k]

// ---------------- float atomic max (signed-max / unsigned-min trick) ----------
__device__ __forceinline__ void atomicMaxF(float* a, float v) {
    if (v >= 0.0f) atomicMax((int*)a, __float_as_int(v));
    else           atomicMin((unsigned int*)a, __float_as_uint(v));
}

// ---------------- HMMA m16n8k16 bf16 ------------------------------------------
__device__ __forceinline__ void mma16816(float& d0, float& d1, float& d2, float& d3,
                                         unsigned a0, unsigned a1, unsigned a2, unsigned a3,
                                         unsigned b0, unsigned b1)
{
    asm volatile(
        "mma.sync.aligned.m16n8k16.row.col.f32.bf16.bf16.f32 "
        "{%0,%1,%2,%3},{%4,%5,%6,%7},{%8,%9},{%0,%1,%2,%3};\n"
        : "+f"(d0), "+f"(d1), "+f"(d2), "+f"(d3)
        : "r"(a0), "r"(a1), "r"(a2), "r"(a3), "r"(b0), "r"(b1));
}

// ---------------- prep: Wc from W1 --------------------------------------------
__global__ void prep_kernel(const float* __restrict__ W1, float* __restrict__ Wc) {
    int k = blockIdx.x;
    int j = threadIdx.x;
    if (j < C) Wc[k * 256 + j] = W1[k * C + j] - W1[(C + k) * C + j];
    else       Wc[k * 256 + j] = W1[(C + k) * C + (j - C)];
}

// ---------------- prep: split W2^T into bf16 hi/lo planes ----------------------
__global__ void w2split_kernel(const float* __restrict__ W2,
                               __nv_bfloat16* __restrict__ hi,
                               __nv_bfloat16* __restrict__ lo) {
    int n = blockIdx.x;
    int k = threadIdx.x;
    float w = W2[k * C + n];
    __nv_bfloat16 h = __float2bfloat16(w);
    hi[n * C + k] = h;
    lo[n * C + k] = __float2bfloat16(w - __bfloat162float(h));
}

// ---------------- node GEMM: pq = x @ Wc (+ b1 on p half) ---------------------
__global__ void __launch_bounds__(256) node_gemm_kernel(
    const float* __restrict__ x, const float* __restrict__ Wc,
    const float* __restrict__ b1, float* __restrict__ pq, int N)
{
    __shared__ float xs[32 * C];
    int m0 = blockIdx.x * 32;
    int tid = threadIdx.x;

    for (int i = tid; i < 32 * C / 4; i += 256) {
        int r = i / (C / 4);
        int cc = i % (C / 4);
        float4 v = make_float4(0.f, 0.f, 0.f, 0.f);
        if (m0 + r < N) v = ((const float4*)(x + (size_t)(m0 + r) * C))[cc];
        ((float4*)xs)[i] = v;
    }
    __syncthreads();

    int col = tid;
    float acc[32];
#pragma unroll
    for (int r = 0; r < 32; r++) acc[r] = 0.f;

#pragma unroll 4
    for (int k = 0; k < C; k++) {
        float w = Wc[k * 256 + col];
#pragma unroll
        for (int r = 0; r < 32; r++) acc[r] = fmaf(xs[r * C + k], w, acc[r]);
    }

    float bias = (col < C) ? b1[col] : 0.f;
#pragma unroll
    for (int r = 0; r < 32; r++)
        if (m0 + r < N) pq[(size_t)(m0 + r) * 256 + col] = acc[r] + bias;
}

// ---------------- edge GEMM (tensor cores, split-bf16) + max aggregation ------
// 512 threads / 16 warps. Warp w: channels ((w&7)*16 .. +16), edges ((w>>3)*64 .. +64).
__global__ void __launch_bounds__(512, 1) edge_mma_kernel(
    const float* __restrict__ pq, const int* __restrict__ src,
    const int* __restrict__ dst,
    const __nv_bfloat16* __restrict__ W2hi, const __nv_bfloat16* __restrict__ W2lo,
    float* __restrict__ agg, int E)
{
    extern __shared__ char smraw[];
    __nv_bfloat16* h_hi = (__nv_bfloat16*)smraw;           // [128][HST]
    __nv_bfloat16* h_lo = h_hi + TE * HST;                 // [128][HST]
    float* DT = (float*)(h_lo + TE * HST);                 // [128][DST]  (u^T)
    __shared__ int sidx[2 * TE];

    int tid = threadIdx.x;
    int wid = tid >> 5, lane = tid & 31;
    int g = lane >> 2, tig = lane & 3;
    int m0 = (wid & 7) * 16;      // 16 output channels per warp
    int ebase = (wid >> 3) * 64;  // edge half

    // Preload A fragments (W2^T, both planes, all 8 k-steps) into registers.
    unsigned ah[8][4], al[8][4];
    {
        const unsigned* Hp = (const unsigned*)W2hi;
        const unsigned* Lp = (const unsigned*)W2lo;
#pragma unroll
        for (int ks = 0; ks < 8; ks++) {
            int k0 = ks * 16;
            int i00 = (m0 + g) * (C / 2) + (k0 + tig * 2) / 2;
            ah[ks][0] = Hp[i00];
            ah[ks][1] = Hp[i00 + 8 * (C / 2)];
            ah[ks][2] = Hp[i00 + 4];
            ah[ks][3] = Hp[i00 + 8 * (C / 2) + 4];
            al[ks][0] = Lp[i00];
            al[ks][1] = Lp[i00 + 8 * (C / 2)];
            al[ks][2] = Lp[i00 + 4];
            al[ks][3] = Lp[i00 + 8 * (C / 2) + 4];
        }
    }

    int ntiles = (E + TE - 1) / TE;
    for (int tile = blockIdx.x; tile < ntiles; tile += gridDim.x) {
        int e0 = tile * TE;
        __syncthreads();   // prev tile fully consumed (h, sidx free)

        // load indices (threads 0..255)
        if (tid < 2 * TE) {
            int e = (tid < TE) ? tid : (tid - TE);
            int gi = e0 + e;
            const int* arr = (tid < TE) ? dst : src;
            sidx[tid] = (gi < E) ? arr[gi] : 0;
        }
        __syncthreads();

        // gather + relu + bf16 split: 4 threads/edge, 32 channels each
        {
            int e = tid >> 2;
            int ch = (tid & 3) * 32;
            const float4* prow = (const float4*)(pq + (size_t)sidx[e] * 256 + ch);
            const float4* qrow = (const float4*)(pq + (size_t)sidx[TE + e] * 256 + C + ch);
            unsigned* hhp = (unsigned*)(h_hi + e * HST + ch);
            unsigned* hlp = (unsigned*)(h_lo + e * HST + ch);
#pragma unroll
            for (int half = 0; half < 2; half++) {
                float4 a[4], b[4];
#pragma unroll
                for (int i = 0; i < 4; i++) { a[i] = prow[half * 4 + i]; b[i] = qrow[half * 4 + i]; }
#pragma unroll
                for (int i = 0; i < 4; i++) {
                    float v0 = fmaxf(a[i].x + b[i].x, 0.f);
                    float v1 = fmaxf(a[i].y + b[i].y, 0.f);
                    float v2 = fmaxf(a[i].z + b[i].z, 0.f);
                    float v3 = fmaxf(a[i].w + b[i].w, 0.f);
                    __nv_bfloat162 hA = __floats2bfloat162_rn(v0, v1);
                    __nv_bfloat162 hB = __floats2bfloat162_rn(v2, v3);
                    __nv_bfloat162 lA = __floats2bfloat162_rn(v0 - __bfloat162float(hA.x),
                                                              v1 - __bfloat162float(hA.y));
                    __nv_bfloat162 lB = __floats2bfloat162_rn(v2 - __bfloat162float(hB.x),
                                                              v3 - __bfloat162float(hB.y));
                    int o = (half * 4 + i) * 2;
                    hhp[o + 0] = *(unsigned*)&hA;
                    hhp[o + 1] = *(unsigned*)&hB;
                    hlp[o + 0] = *(unsigned*)&lA;
                    hlp[o + 1] = *(unsigned*)&lB;
                }
            }
        }
        __syncthreads();

        // MMA: 8 edge-subtiles of 8 (this warp's 64 edges), K=128, 3 split terms
#pragma unroll 1
        for (int et = 0; et < 8; et++) {
            int e0t = ebase + et * 8;
            float d0 = 0.f, d1 = 0.f, d2 = 0.f, d3 = 0.f;
#pragma unroll
            for (int ks = 0; ks < 8; ks++) {
                int k0 = ks * 16;
                const unsigned* bhp = (const unsigned*)(h_hi + (e0t + g) * HST + k0 + tig * 2);
                const unsigned* blp = (const unsigned*)(h_lo + (e0t + g) * HST + k0 + tig * 2);
                unsigned bh0 = bhp[0], bh1 = bhp[4];
                unsigned bl0 = blp[0], bl1 = blp[4];
                mma16816(d0, d1, d2, d3, ah[ks][0], ah[ks][1], ah[ks][2], ah[ks][3], bh0, bh1);
                mma16816(d0, d1, d2, d3, al[ks][0], al[ks][1], al[ks][2], al[ks][3], bh0, bh1);
                mma16816(d0, d1, d2, d3, ah[ks][0], ah[ks][1], ah[ks][2], ah[ks][3], bl0, bl1);
            }
            *(float2*)&DT[(m0 + g) * DST + e0t + tig * 2]     = make_float2(d0, d1);
            *(float2*)&DT[(m0 + g + 8) * DST + e0t + tig * 2] = make_float2(d2, d3);
        }
        __syncthreads();

        // epilogue: edge-major lanes -> conflict-free DT column reads
        {
            int e = tid & 127;
            int ch = (tid >> 7) * 32;
            if (e0 + e < E) {
                int dn = sidx[e];
                float* arow = agg + (size_t)dn * C + ch;
#pragma unroll
                for (int i = 0; i < 8; i++) {
                    float4 cur = ((const float4*)arow)[i];
                    float v0 = DT[(ch + i * 4 + 0) * DST + e];
                    float v1 = DT[(ch + i * 4 + 1) * DST + e];
                    float v2 = DT[(ch + i * 4 + 2) * DST + e];
                    float v3 = DT[(ch + i * 4 + 3) * DST + e];
                    if (!(v0 <= cur.x)) atomicMaxF(arow + i * 4 + 0, v0);
                    if (!(v1 <= cur.y)) atomicMaxF(arow + i * 4 + 1, v1);
                    if (!(v2 <= cur.z)) atomicMaxF(arow + i * 4 + 2, v2);
                    if (!(v3 <= cur.w)) atomicMaxF(arow + i * 4 + 3, v3);
                }
            }
        }
    }
}

// ---------------- finalize: handle empty nodes, +b2, optional relu ------------
__global__ void finalize_kernel(const float* __restrict__ agg,
                                const float* __restrict__ b2,
                                float* __restrict__ out, int N, int do_relu)
{
    int idx = blockIdx.x * blockDim.x + threadIdx.x;
    if (idx >= N * C) return;
    int c = idx & (C - 1);
    float v = agg[idx];
    float o = isfinite(v) ? (v + b2[c]) : 0.f;
    if (do_relu) o = fmaxf(o, 0.f);
    out[idx] = o;
}

// ---------------- launch -------------------------------------------------------
extern "C" void kernel_launch(void* const* d_in, const int* in_sizes, int n_in,
                              void* d_out, int out_size)
{
    const float* x  = (const float*)d_in[0];
    const int*   ei = (const int*)d_in[1];
    int N = in_sizes[0] / C;
    int E = in_sizes[1] / 2;
    const int* srcp = ei;
    const int* dstp = ei + E;

    float *pq, *aggp, *xcur, *Wc;
    __nv_bfloat16 *w2hi, *w2lo;
    cudaGetSymbolAddress((void**)&pq,   g_pq);
    cudaGetSymbolAddress((void**)&aggp, g_agg);
    cudaGetSymbolAddress((void**)&xcur, g_x);
    cudaGetSymbolAddress((void**)&Wc,   g_Wc);
    cudaGetSymbolAddress((void**)&w2hi, g_w2hi);
    cudaGetSymbolAddress((void**)&w2lo, g_w2lo);

    const size_t SMEM = (size_t)(2 * TE * HST) * sizeof(__nv_bfloat16)
                      + (size_t)(C * DST) * sizeof(float);
    cudaFuncSetAttribute(edge_mma_kernel, cudaFuncAttributeMaxDynamicSharedMemorySize, (int)SMEM);

    const float* Ws[3][4] = {
        {(const float*)d_in[2],  (const float*)d_in[3],  (const float*)d_in[4],  (const float*)d_in[5]},
        {(const float*)d_in[6],  (const float*)d_in[7],  (const float*)d_in[8],  (const float*)d_in[9]},
        {(const float*)d_in[10], (const float*)d_in[11], (const float*)d_in[12], (const float*)d_in[13]},
    };

    const float* xin = x;
    for (int l = 0; l < 3; l++) {
        const float* W1 = Ws[l][0];
        const float* b1 = Ws[l][1];
        const float* W2 = Ws[l][2];
        const float* b2 = Ws[l][3];
        float* xout = (l == 2) ? (float*)d_out : xcur;

        prep_kernel<<<C, 256>>>(W1, Wc);
        w2split_kernel<<<C, C>>>(W2, w2hi, w2lo);
        node_gemm_kernel<<<(N + 31) / 32, 256>>>(xin, Wc, b1, pq, N);
        cudaMemsetAsync(aggp, 0xFF, (size_t)N * C * sizeof(float));
        edge_mma_kernel<<<148, 512, SMEM>>>(pq, srcp, dstp, w2hi, w2lo, aggp, E);
        finalize_kernel<<<(N * C + 255) / 256, 256>>>(aggp, b2, xout, N, (l < 2) ? 1 : 0);

        xin = xcur;
    }
}